// round 16
// baseline (speedup 1.0000x reference)
#include <cuda_runtime.h>
#include <math.h>
#include <stdint.h>

#define SN    255
#define B_    64
#define EMB   200
#define HID   300
#define NROWS (SN * B_)     // 16320
#define NC    1200
#define H_LD  304
#define KCH_E 13
#define KCH_U 19
#define NBG0  160
#define NBGI  128
#define NBGF  48

// ---- device scratch (zero-initialized at load; padding cols stay 0) ----
__device__ float g_wx[NROWS * NC];
__device__ float g_H [NROWS * H_LD + 64];
__device__ float g_Hs[64 * B_ * H_LD + 64];
__device__ float g_C [NROWS * HID];
__device__ float g_Ti[64 * B_ * 900];
__device__ float g_Tf[128 * B_ * 300];
__device__ uint4 g_Bw_f[NBG0 * KCH_E * 32];
__device__ uint4 g_Bi_f[NBGI * KCH_U * 32];
__device__ uint4 g_Bf_f[NBGF * KCH_U * 32];
__device__ float g_bias[NC];
__device__ unsigned g_grpCnt[32];   // per-parent-pair tile counters (fused levels)

__device__ __forceinline__ uint32_t f2tf(float x) {
    uint32_t u; asm("cvt.rna.tf32.f32 %0, %1;" : "=r"(u) : "f"(x)); return u;
}

// ---- fast gates ----
__device__ __forceinline__ float fsig(float x) {
    return __fdividef(1.0f, 1.0f + __expf(-x));
}
__device__ __forceinline__ float ftanh(float x) {
    float t = __expf(-2.0f * fabsf(x));
    float r = __fdividef(1.0f - t, 1.0f + t);
    return copysignf(r, x);
}
__device__ __forceinline__ float4 f4add(float4 a, float4 b) {
    return make_float4(a.x + b.x, a.y + b.y, a.z + b.z, a.w + b.w);
}
__device__ __forceinline__ float4 f4sig(float4 a) {
    return make_float4(fsig(a.x), fsig(a.y), fsig(a.z), fsig(a.w));
}
__device__ __forceinline__ float4 f4tanh(float4 a) {
    return make_float4(ftanh(a.x), ftanh(a.y), ftanh(a.z), ftanh(a.w));
}
__device__ __forceinline__ float4 f4mul(float4 a, float4 b) {
    return make_float4(a.x * b.x, a.y * b.y, a.z * b.z, a.w * b.w);
}
__device__ __forceinline__ float4 f4fma(float4 a, float4 b, float4 c) {
    return make_float4(fmaf(a.x, b.x, c.x), fmaf(a.y, b.y, c.y),
                       fmaf(a.z, b.z, c.z), fmaf(a.w, b.w, c.w));
}

#define CPA16(dst, src) \
    asm volatile("cp.async.ca.shared.global [%0], [%1], 16;" :: "r"(dst), "l"(src))
#define CPA16Z(dst, src, sz) \
    asm volatile("cp.async.ca.shared.global [%0], [%1], 16, %2;" :: "r"(dst), "l"(src), "r"(sz))
#define CPCOMMIT() asm volatile("cp.async.commit_group;")
#define CPWAIT(n)  asm volatile("cp.async.wait_group %0;" :: "n"(n))

// ---------------------------------------------------------------------------
// prep_w: Bw fragments + bias (critical path). prep_u: Bi/Bf (overlapped s2).
// ---------------------------------------------------------------------------
__global__ void prep_w(const float* __restrict__ W_iou, const float* __restrict__ W_f,
                       const float* __restrict__ b_iou, const float* __restrict__ b_f)
{
    int idx = blockIdx.x * blockDim.x + threadIdx.x;
    if (idx < NBG0 * KCH_E * 32) {
        int ln = idx & 31, kch = (idx >> 5) % KCH_E, nbg = idx / (32 * KCH_E);
        int n = nbg * 8 + (ln >> 2), tk = ln & 3, kb = kch * 16;
        uint4 v; uint32_t* vp = (uint32_t*)&v;
        #pragma unroll
        for (int q = 0; q < 4; ++q) {
            int k = kb + q * 4 + tk;
            float f = 0.0f;
            if (k < EMB && n < NC)
                f = (n < 900) ? W_iou[k * 900 + n] : W_f[k * 300 + (n - 900)];
            vp[q] = f2tf(f);
        }
        g_Bw_f[idx] = v;
    }
    if (idx < NC) g_bias[idx] = (idx < 900) ? b_iou[idx] : b_f[idx - 900];
}

__global__ void prep_u(const float* __restrict__ U_iou, const float* __restrict__ U_f)
{
    int idx = blockIdx.x * blockDim.x + threadIdx.x;
    if (idx < NBGI * KCH_U * 32) {
        int ln = idx & 31, kch = (idx >> 5) % KCH_U, nbg = idx / (32 * KCH_U);
        int n = nbg * 8 + (ln >> 2), tk = ln & 3, kb = kch * 16;
        uint4 v; uint32_t* vp = (uint32_t*)&v;
        #pragma unroll
        for (int q = 0; q < 4; ++q) {
            int k = kb + q * 4 + tk;
            float f = (k < HID && n < 900) ? U_iou[k * 900 + n] : 0.0f;
            vp[q] = f2tf(f);
        }
        g_Bi_f[idx] = v;
    }
    if (idx < NBGF * KCH_U * 32) {
        int ln = idx & 31, kch = (idx >> 5) % KCH_U, nbg = idx / (32 * KCH_U);
        int n = nbg * 8 + (ln >> 2), tk = ln & 3, kb = kch * 16;
        uint4 v; uint32_t* vp = (uint32_t*)&v;
        #pragma unroll
        for (int q = 0; q < 4; ++q) {
            int k = kb + q * 4 + tk;
            float f = (k < HID && n < 300) ? U_f[k * 300 + n] : 0.0f;
            vp[q] = f2tf(f);
        }
        g_Bf_f[idx] = v;
    }
}

#define MMA_STEP(ACC, AQ, B0, B1)                                              \
    asm("mma.sync.aligned.m16n8k8.row.col.f32.tf32.tf32.f32 "                  \
        "{%0,%1,%2,%3},{%4,%5,%6,%7},{%8,%9},{%0,%1,%2,%3};"                   \
        : "+f"((ACC)[0]), "+f"((ACC)[1]), "+f"((ACC)[2]), "+f"((ACC)[3])       \
        : "r"((AQ)[0]), "r"((AQ)[1]), "r"((AQ)[2]), "r"((AQ)[3]),              \
          "r"(B0), "r"(B1))

#define LDSM_A(AQ, ASBASE, R0, KB)                                             \
    do {                                                                       \
        const float* _p = (ASBASE) +                                           \
            ((R0) + (lane & 7) + ((lane >> 3) & 1) * 8) * 20 +                 \
            (KB) * 8 + (lane >> 4) * 4;                                        \
        uint32_t _ad = (uint32_t)__cvta_generic_to_shared(_p);                 \
        asm volatile("ldmatrix.sync.aligned.m8n8.x4.shared.b16 "               \
                     "{%0,%1,%2,%3},[%4];"                                     \
                     : "=r"((AQ)[0]), "=r"((AQ)[1]), "=r"((AQ)[2]), "=r"((AQ)[3]) \
                     : "r"(_ad));                                              \
    } while (0)

// ---------------------------------------------------------------------------
// gemm_wx: wx rows [rowOff, rowOff+Mpart) = emb @ [W_iou|W_f] + bias.
// ---------------------------------------------------------------------------
__global__ __launch_bounds__(256, 2) void gemm_wx(
    const float* __restrict__ embedTab, const int* __restrict__ xg,
    int rowOff, int Mpart)
{
    extern __shared__ char smem[];
    float (*As)[128][20] = (float (*)[128][20])smem;
    uint4 (*Bs)[16][32]  = (uint4 (*)[16][32])(smem + 3 * 128 * 80);
    const float** arows  = (const float**)(smem + 3 * 128 * 80 + 3 * 16 * 32 * 16);

    const int tid = threadIdx.x;
    const int rowBase = rowOff + blockIdx.x * 128;
    const int colBase = blockIdx.y * 128;
    const int Mend = rowOff + Mpart;

    if (tid < 128) {
        int m = rowBase + tid;
        int mc = (m < Mend) ? m : (Mend - 1);
        arows[tid] = embedTab + (size_t)xg[mc] * EMB;
    }
    __syncthreads();

    const int lane = tid & 31, warp = tid >> 5;
    const int wm = (warp & 3) * 32, wn = (warp >> 2) * 64;
    const int nbW = wn >> 3;
    const int tg = lane >> 2, tk = lane & 3;
    const int nbgBase = colBase >> 3;

    float acc[2][8][4] = {};

#define FILL_WX(ST, KC)                                                         \
    do {                                                                        \
        int _k0 = (KC) * 16;                                                    \
        _Pragma("unroll")                                                       \
        for (int _i = 0; _i < 2; ++_i) {                                        \
            int _e = tid + _i * 256, _r = _e >> 2, _c = _e & 3;                 \
            uint32_t _d = (uint32_t)__cvta_generic_to_shared(&As[ST][_r][_c*4]);\
            const float* _s = arows[_r] + _k0 + _c * 4;                         \
            int _vb = EMB - (_k0 + _c * 4);                                     \
            int _sz = (_vb >= 4) ? 16 : ((_vb > 0) ? _vb * 4 : 0);              \
            CPA16Z(_d, _s, _sz);                                                \
        }                                                                       \
        _Pragma("unroll")                                                       \
        for (int _i = 0; _i < 2; ++_i) {                                        \
            int _e = tid + _i * 256, _nb = _e >> 5, _ln = _e & 31;              \
            uint32_t _d = (uint32_t)__cvta_generic_to_shared(&Bs[ST][_nb][_ln]);\
            CPA16(_d, g_Bw_f + ((size_t)(nbgBase + _nb) * KCH_E + (KC)) * 32 + _ln); \
        }                                                                       \
        CPCOMMIT();                                                             \
    } while (0)

    FILL_WX(0, 0);
    FILL_WX(1, 1);

    for (int kch = 0; kch < KCH_E; ++kch) {
        const int s = kch % 3;
        if (kch + 1 < KCH_E) { CPWAIT(1); } else { CPWAIT(0); }
        __syncthreads();
        if (kch + 2 < KCH_E) FILL_WX((kch + 2) % 3, kch + 2);

        uint32_t a[2][2][4];
        #pragma unroll
        for (int kb = 0; kb < 2; ++kb)
            #pragma unroll
            for (int mf = 0; mf < 2; ++mf)
                LDSM_A(a[kb][mf], &As[s][0][0], wm + mf * 16, kb);

        #pragma unroll
        for (int nf = 0; nf < 8; ++nf) {
            uint4 bq = Bs[s][nbW + nf][lane];
            #pragma unroll
            for (int mf = 0; mf < 2; ++mf) {
                MMA_STEP(acc[mf][nf], a[0][mf], bq.x, bq.y);
                MMA_STEP(acc[mf][nf], a[1][mf], bq.z, bq.w);
            }
        }
    }
#undef FILL_WX

    #pragma unroll
    for (int mf = 0; mf < 2; ++mf)
        #pragma unroll
        for (int nf = 0; nf < 8; ++nf) {
            int row = rowBase + wm + mf * 16 + tg;
            int col = colBase + wn + nf * 8 + tk * 2;
            if (col < NC) {
                float b0 = g_bias[col], b1 = g_bias[col + 1];
                if (row < Mend)
                    *(float2*)(g_wx + (size_t)row * NC + col) =
                        make_float2(acc[mf][nf][0] + b0, acc[mf][nf][1] + b1);
                if (row + 8 < Mend)
                    *(float2*)(g_wx + (size_t)(row + 8) * NC + col) =
                        make_float2(acc[mf][nf][2] + b0, acc[mf][nf][3] + b1);
            }
        }
}

// ---------------------------------------------------------------------------
// Device body for one level-GEMM tile.
// ---------------------------------------------------------------------------
__device__ __forceinline__ void dev_level_tile(
    char* smem, int p0, int np, bool isF, int rowBase, int colBase)
{
    float (*As)[128][20] = (float (*)[128][20])smem;
    uint4 (*Bs)[16][32]  = (uint4 (*)[16][32])(smem + 3 * 128 * 80);

    const int tid = threadIdx.x;
    const int Mrows = isF ? np * 128 : np * 64;
    const int Nout = isF ? 300 : 900;
    const uint4* gB = isF ? g_Bf_f : g_Bi_f;
    float* Cout = isF ? g_Tf : g_Ti;

    const int lane = tid & 31, warp = tid >> 5;
    const int wm = (warp & 3) * 32, wn = (warp >> 2) * 64;
    const int nbW = wn >> 3;
    const int tg = lane >> 2, tk = lane & 3;
    const int nbgBase = colBase >> 3;

    const int ar = tid >> 1;
    const int ac = (tid & 1) << 1;
    int arow = rowBase + ar; if (arow >= Mrows) arow = Mrows - 1;
    const float* asrc = isF
        ? g_H  + (size_t)((2 * p0 + 1) * B_ + arow) * H_LD
        : g_Hs + (size_t)arow * H_LD;

    float acc[2][8][4] = {};

#define FILL_LV(ST, KC)                                                         \
    do {                                                                        \
        int _k0 = (KC) * 16;                                                    \
        _Pragma("unroll")                                                       \
        for (int _i = 0; _i < 2; ++_i) {                                        \
            int _c = ac + _i;                                                   \
            uint32_t _d = (uint32_t)__cvta_generic_to_shared(&As[ST][ar][_c*4]);\
            CPA16(_d, asrc + _k0 + _c * 4);                                     \
        }                                                                       \
        _Pragma("unroll")                                                       \
        for (int _i = 0; _i < 2; ++_i) {                                        \
            int _e = tid + _i * 256, _nb = _e >> 5, _ln = _e & 31;              \
            uint32_t _d = (uint32_t)__cvta_generic_to_shared(&Bs[ST][_nb][_ln]);\
            CPA16(_d, gB + ((size_t)(nbgBase + _nb) * KCH_U + (KC)) * 32 + _ln);\
        }                                                                       \
        CPCOMMIT();                                                             \
    } while (0)

    FILL_LV(0, 0);
    FILL_LV(1, 1);

    for (int kch = 0; kch < KCH_U; ++kch) {
        const int s = kch % 3;
        if (kch + 1 < KCH_U) { CPWAIT(1); } else { CPWAIT(0); }
        __syncthreads();
        if (kch + 2 < KCH_U) FILL_LV((kch + 2) % 3, kch + 2);

        uint32_t a[2][2][4];
        #pragma unroll
        for (int kb = 0; kb < 2; ++kb)
            #pragma unroll
            for (int mf = 0; mf < 2; ++mf)
                LDSM_A(a[kb][mf], &As[s][0][0], wm + mf * 16, kb);

        #pragma unroll
        for (int nf = 0; nf < 8; ++nf) {
            uint4 bq = Bs[s][nbW + nf][lane];
            #pragma unroll
            for (int mf = 0; mf < 2; ++mf) {
                MMA_STEP(acc[mf][nf], a[0][mf], bq.x, bq.y);
                MMA_STEP(acc[mf][nf], a[1][mf], bq.z, bq.w);
            }
        }
    }
#undef FILL_LV

    #pragma unroll
    for (int mf = 0; mf < 2; ++mf)
        #pragma unroll
        for (int nf = 0; nf < 8; ++nf) {
            int row = rowBase + wm + mf * 16 + tg;
            int col = colBase + wn + nf * 8 + tk * 2;
            if (col < Nout) {
                if (row < Mrows)
                    *(float2*)(Cout + (size_t)row * Nout + col) =
                        make_float2(acc[mf][nf][0], acc[mf][nf][1]);
                if (row + 8 < Mrows)
                    *(float2*)(Cout + (size_t)(row + 8) * Nout + col) =
                        make_float2(acc[mf][nf][2], acc[mf][nf][3]);
            }
        }
}

// Standalone level GEMM (d=6 and root).
__global__ __launch_bounds__(256, 2) void level_gemm(int p0, int np)
{
    extern __shared__ char smem[];
    const bool isF = (blockIdx.y >= 8);
    const int Mrows = isF ? np * 128 : np * 64;
    const int rowBase = blockIdx.x * 128;
    if (rowBase >= Mrows) return;
    const int colBase = (isF ? (blockIdx.y - 8) : blockIdx.y) * 128;
    dev_level_tile(smem, p0, np, isF, rowBase, colBase);
}

// ---------------------------------------------------------------------------
// Leaves (float4, sibling-paired).
// ---------------------------------------------------------------------------
__global__ void leaf_kernel()
{
    int idx = blockIdx.x * blockDim.x + threadIdx.x;
    if (idx >= 64 * B_ * 75) return;
    int q = idx % 75;
    int r = idx / 75;
    int b = r % B_;
    int j = r / B_;

    float4 hs = make_float4(0.f, 0.f, 0.f, 0.f);
    #pragma unroll
    for (int s = 0; s < 2; ++s) {
        int row = (127 + 2 * j + s) * B_ + b;
        const float4* wx = (const float4*)(g_wx + (size_t)row * NC);
        float4 iv = f4sig (wx[q]);
        float4 ov = f4sig (wx[75 + q]);
        float4 uv = f4tanh(wx[150 + q]);
        float4 c4 = f4mul(iv, uv);
        float4 h4 = f4mul(ov, f4tanh(c4));
        ((float4*)(g_C + (size_t)row * HID))[q] = c4;
        ((float4*)(g_H + (size_t)row * H_LD))[q] = h4;
        hs = f4add(hs, h4);
    }
    ((float4*)(g_Hs + (size_t)r * H_LD))[q] = hs;
}

// ---------------------------------------------------------------------------
// Gate math (float4).
// ---------------------------------------------------------------------------
__device__ __forceinline__ float4 node_gate4(int p0, int pi, int b, int q, float4* cOut)
{
    int p = p0 + pi;
    const float4* wx = (const float4*)(g_wx + (size_t)(p * B_ + b) * NC);
    const float4* ti = (const float4*)(g_Ti + (size_t)(pi * B_ + b) * 900);
    float4 iv = f4sig (f4add(wx[q],       ti[q]));
    float4 ov = f4sig (f4add(wx[75 + q],  ti[75 + q]));
    float4 uv = f4tanh(f4add(wx[150 + q], ti[150 + q]));
    float4 wf = wx[225 + q];
    const float4* tl = (const float4*)(g_Tf + (size_t)((2 * pi    ) * B_ + b) * 300);
    const float4* tr = (const float4*)(g_Tf + (size_t)((2 * pi + 1) * B_ + b) * 300);
    float4 fl = f4sig(f4add(wf, tl[q]));
    float4 fr = f4sig(f4add(wf, tr[q]));
    int lc = 2 * p + 1, rc = 2 * p + 2;
    const float4* cl = (const float4*)(g_C + (size_t)(lc * B_ + b) * HID);
    const float4* cr = (const float4*)(g_C + (size_t)(rc * B_ + b) * HID);
    float4 fc = f4fma(fl, cl[q], f4mul(fr, cr[q]));
    float4 c = f4fma(iv, uv, fc);
    *cOut = c;
    return f4mul(ov, f4tanh(c));
}

__device__ __forceinline__ void dev_pw_elem(int p0, int idx)
{
    int q = idx % 75;
    int r = idx / 75;
    int b = r % B_;
    int i = r / B_;
    float4 cL, cR;
    float4 hL = node_gate4(p0, 2 * i,     b, q, &cL);
    float4 hR = node_gate4(p0, 2 * i + 1, b, q, &cR);
    int pL = p0 + 2 * i, pR = pL + 1;
    ((float4*)(g_C + (size_t)(pL * B_ + b) * HID))[q] = cL;
    ((float4*)(g_C + (size_t)(pR * B_ + b) * HID))[q] = cR;
    ((float4*)(g_H + (size_t)(pL * B_ + b) * H_LD))[q] = hL;
    ((float4*)(g_H + (size_t)(pR * B_ + b) * H_LD))[q] = hR;
    ((float4*)(g_Hs + (size_t)r * H_LD))[q] = f4add(hL, hR);
}

// Standalone pw (d=6 only).
__global__ void level_pw_pair(int p0, int np)
{
    int idx = blockIdx.x * blockDim.x + threadIdx.x;
    if (idx < (np >> 1) * B_ * 75) dev_pw_elem(p0, idx);
}

// ---------------------------------------------------------------------------
// Fused level GEMM + pw (levels d=5..1, np in {32,16,8,4,2}).
// Each parent pair g is fed by exactly 14 tiles (8 iou + 6 f). The 14th
// finisher runs that pair's pointwise gates (threadFenceReduction idiom —
// no block ever waits; deadlock-free by construction).
// ---------------------------------------------------------------------------
__global__ __launch_bounds__(256, 2) void level_gemm_pw(int p0, int np)
{
    extern __shared__ char smem[];
    __shared__ int sLast;

    const bool isF = (blockIdx.y >= 8);
    const int Mrows = isF ? np * 128 : np * 64;
    const int rowBase = blockIdx.x * 128;
    if (rowBase >= Mrows) return;
    const int colBase = (isF ? (blockIdx.y - 8) : blockIdx.y) * 128;

    dev_level_tile(smem, p0, np, isF, rowBase, colBase);

    const int grp = isF ? ((int)blockIdx.x >> 1) : (int)blockIdx.x;

    __syncthreads();                     // all tile stores issued block-wide
    if (threadIdx.x == 0) {
        __threadfence();                 // release this block's gmem writes
        unsigned old = atomicAdd(&g_grpCnt[grp], 1u);
        sLast = (old == 13u);
        if (sLast) {
            g_grpCnt[grp] = 0;           // unique toucher; reset for next level
            __threadfence();             // acquire other blocks' tile writes
        }
    }
    __syncthreads();
    if (!sLast) return;

    const int base = grp * (B_ * 75);    // 4800 float4-elements per pair
    for (int e = threadIdx.x; e < B_ * 75; e += 256)
        dev_pw_elem(p0, base + e);
}

// ---------------------------------------------------------------------------
// root_out: fused root gates + output head (log_softmax over 2 classes).
// ---------------------------------------------------------------------------
__global__ __launch_bounds__(32) void root_out(
    const float* __restrict__ W_out, const float* __restrict__ b_out,
    float* __restrict__ out)
{
    const int b = blockIdx.x;
    const int tid = threadIdx.x;
    float l0 = 0.f, l1 = 0.f;
    for (int q = tid; q < 75; q += 32) {
        float4 c4;
        float4 h4 = node_gate4(0, 0, b, q, &c4);
        int n = q * 4;
        l0 = fmaf(h4.x, W_out[n * 2 + 0], l0); l1 = fmaf(h4.x, W_out[n * 2 + 1], l1);
        l0 = fmaf(h4.y, W_out[n * 2 + 2], l0); l1 = fmaf(h4.y, W_out[n * 2 + 3], l1);
        l0 = fmaf(h4.z, W_out[n * 2 + 4], l0); l1 = fmaf(h4.z, W_out[n * 2 + 5], l1);
        l0 = fmaf(h4.w, W_out[n * 2 + 6], l0); l1 = fmaf(h4.w, W_out[n * 2 + 7], l1);
    }
    #pragma unroll
    for (int o = 16; o > 0; o >>= 1) {
        l0 += __shfl_down_sync(0xffffffffu, l0, o);
        l1 += __shfl_down_sync(0xffffffffu, l1, o);
    }
    if (tid == 0) {
        l0 += b_out[0]; l1 += b_out[1];
        float m   = fmaxf(l0, l1);
        float lse = m + logf(expf(l0 - m) + expf(l1 - m));
        out[b * 2 + 0] = l0 - lse;
        out[b * 2 + 1] = l1 - lse;
    }
}

// ---------------------------------------------------------------------------
extern "C" void kernel_launch(void* const* d_in, const int* in_sizes, int n_in,
                              void* d_out, int out_size)
{
    (void)in_sizes; (void)n_in; (void)out_size;
    const int*   x     = (const int*)  d_in[0];
    const float* embed = (const float*)d_in[3];
    const float* W_iou = (const float*)d_in[4];
    const float* U_iou = (const float*)d_in[5];
    const float* b_iou = (const float*)d_in[6];
    const float* W_f   = (const float*)d_in[7];
    const float* U_f   = (const float*)d_in[8];
    const float* b_f   = (const float*)d_in[9];
    const float* W_out = (const float*)d_in[10];
    const float* b_out = (const float*)d_in[11];

    const int SMEM_WX = 3 * 128 * 80 + 3 * 16 * 32 * 16 + 128 * 8;
    const int SMEM_LV = 3 * 128 * 80 + 3 * 16 * 32 * 16;

    static cudaStream_t s2 = 0;
    static cudaEvent_t evFork = 0, evPrep = 0, evJoin1 = 0, evJoin2 = 0;
    static int inited = 0;
    if (!inited) {
        cudaFuncSetAttribute(gemm_wx,       cudaFuncAttributeMaxDynamicSharedMemorySize, SMEM_WX);
        cudaFuncSetAttribute(level_gemm,    cudaFuncAttributeMaxDynamicSharedMemorySize, SMEM_LV);
        cudaFuncSetAttribute(level_gemm_pw, cudaFuncAttributeMaxDynamicSharedMemorySize, SMEM_LV);
        int lo, hi;
        cudaDeviceGetStreamPriorityRange(&lo, &hi);
        cudaStreamCreateWithPriority(&s2, cudaStreamNonBlocking, lo);
        cudaEventCreateWithFlags(&evFork,  cudaEventDisableTiming);
        cudaEventCreateWithFlags(&evPrep,  cudaEventDisableTiming);
        cudaEventCreateWithFlags(&evJoin1, cudaEventDisableTiming);
        cudaEventCreateWithFlags(&evJoin2, cudaEventDisableTiming);
        inited = 1;
    }

    // Critical path: Bw prep -> leaf wx (iou cols only) -> leaf gates -> levels.
    prep_w<<<(NBG0 * KCH_E * 32 + 255) / 256, 256>>>(W_iou, W_f, b_iou, b_f);

    cudaEventRecord(evFork, 0);
    cudaStreamWaitEvent(s2, evFork, 0);
    // s2 (low priority): U prep, then internal wx, deepest parents first.
    prep_u<<<(NBGI * KCH_U * 32 + 255) / 256, 256, 0, s2>>>(U_iou, U_f);
    cudaEventRecord(evPrep, s2);
    gemm_wx<<<dim3(32, 10), 256, SMEM_WX, s2>>>(embed, x, 63 * B_, 64 * B_);  // rows 4032..8127 (parents 63..126)
    cudaEventRecord(evJoin1, s2);
    gemm_wx<<<dim3(32, 10), 256, SMEM_WX, s2>>>(embed, x, 0, 63 * B_);        // rows 0..4031 (parents 0..62)
    cudaEventRecord(evJoin2, s2);

    // Leaf path on stream 0: leaf wx (iou cols < 1024 only).
    gemm_wx<<<dim3(64, 8), 256, SMEM_WX>>>(embed, x, 127 * B_, 128 * B_);
    leaf_kernel<<<(64 * B_ * 75 + 255) / 256, 256>>>();

    cudaStreamWaitEvent(0, evPrep, 0);   // level GEMMs need Bi/Bf
    {   // d = 6 (separate pw; waits for deep internal wx chunk)
        int np = 64, p0 = 63;
        level_gemm<<<dim3(np, 11), 256, SMEM_LV>>>(p0, np);
        cudaStreamWaitEvent(0, evJoin1, 0);
        level_pw_pair<<<((np / 2) * B_ * 75 + 255) / 256, 256>>>(p0, np);
    }

    cudaStreamWaitEvent(0, evJoin2, 0);  // fused pw at d<=5 reads wx of parents 0..62
    for (int d = 5; d >= 1; --d) {
        int np = 1 << d;
        int p0 = np - 1;
        level_gemm_pw<<<dim3(np, 11), 256, SMEM_LV>>>(p0, np);
    }
    level_gemm<<<dim3(1, 11), 256, SMEM_LV>>>(0, 1);
    root_out<<<64, 32>>>(W_out, b_out, (float*)d_out);
}

// round 17
// speedup vs baseline: 1.6215x; 1.6215x over previous
#include <cuda_runtime.h>
#include <math.h>
#include <stdint.h>

#define SN    255
#define B_    64
#define EMB   200
#define HID   300
#define NROWS (SN * B_)     // 16320
#define NC    1200
#define H_LD  304
#define KCH_E 13
#define KCH_U 19
#define NBG0  160
#define NBGI  128
#define NBGF  48

// ---- device scratch (zero-initialized at load; padding cols stay 0) ----
__device__ float g_wx[NROWS * NC];
__device__ float g_H [NROWS * H_LD + 64];
__device__ float g_Hs[64 * B_ * H_LD + 64];
__device__ float g_C [NROWS * HID];
__device__ float g_Ti[64 * B_ * 900];
__device__ float g_Tf[128 * B_ * 300];
__device__ uint4 g_Bw_f[NBG0 * KCH_E * 32];
__device__ uint4 g_Bi_f[NBGI * KCH_U * 32];
__device__ uint4 g_Bf_f[NBGF * KCH_U * 32];
__device__ float g_bias[NC];

__device__ __forceinline__ uint32_t f2tf(float x) {
    uint32_t u; asm("cvt.rna.tf32.f32 %0, %1;" : "=r"(u) : "f"(x)); return u;
}

// ---- fast gates ----
__device__ __forceinline__ float fsig(float x) {
    return __fdividef(1.0f, 1.0f + __expf(-x));
}
__device__ __forceinline__ float ftanh(float x) {
    float t = __expf(-2.0f * fabsf(x));
    float r = __fdividef(1.0f - t, 1.0f + t);
    return copysignf(r, x);
}
__device__ __forceinline__ float4 f4add(float4 a, float4 b) {
    return make_float4(a.x + b.x, a.y + b.y, a.z + b.z, a.w + b.w);
}
__device__ __forceinline__ float4 f4sig(float4 a) {
    return make_float4(fsig(a.x), fsig(a.y), fsig(a.z), fsig(a.w));
}
__device__ __forceinline__ float4 f4tanh(float4 a) {
    return make_float4(ftanh(a.x), ftanh(a.y), ftanh(a.z), ftanh(a.w));
}
__device__ __forceinline__ float4 f4mul(float4 a, float4 b) {
    return make_float4(a.x * b.x, a.y * b.y, a.z * b.z, a.w * b.w);
}
__device__ __forceinline__ float4 f4fma(float4 a, float4 b, float4 c) {
    return make_float4(fmaf(a.x, b.x, c.x), fmaf(a.y, b.y, c.y),
                       fmaf(a.z, b.z, c.z), fmaf(a.w, b.w, c.w));
}

#define CPA16(dst, src) \
    asm volatile("cp.async.ca.shared.global [%0], [%1], 16;" :: "r"(dst), "l"(src))
#define CPA16Z(dst, src, sz) \
    asm volatile("cp.async.ca.shared.global [%0], [%1], 16, %2;" :: "r"(dst), "l"(src), "r"(sz))
#define CPCOMMIT() asm volatile("cp.async.commit_group;")
#define CPWAIT(n)  asm volatile("cp.async.wait_group %0;" :: "n"(n))

// ---------------------------------------------------------------------------
// prep_w: Bw fragments + bias (critical path). prep_u: Bi/Bf (overlapped s2).
// ---------------------------------------------------------------------------
__global__ void prep_w(const float* __restrict__ W_iou, const float* __restrict__ W_f,
                       const float* __restrict__ b_iou, const float* __restrict__ b_f)
{
    int idx = blockIdx.x * blockDim.x + threadIdx.x;
    if (idx < NBG0 * KCH_E * 32) {
        int ln = idx & 31, kch = (idx >> 5) % KCH_E, nbg = idx / (32 * KCH_E);
        int n = nbg * 8 + (ln >> 2), tk = ln & 3, kb = kch * 16;
        uint4 v; uint32_t* vp = (uint32_t*)&v;
        #pragma unroll
        for (int q = 0; q < 4; ++q) {
            int k = kb + q * 4 + tk;
            float f = 0.0f;
            if (k < EMB && n < NC)
                f = (n < 900) ? W_iou[k * 900 + n] : W_f[k * 300 + (n - 900)];
            vp[q] = f2tf(f);
        }
        g_Bw_f[idx] = v;
    }
    if (idx < NC) g_bias[idx] = (idx < 900) ? b_iou[idx] : b_f[idx - 900];
}

__global__ void prep_u(const float* __restrict__ U_iou, const float* __restrict__ U_f)
{
    int idx = blockIdx.x * blockDim.x + threadIdx.x;
    if (idx < NBGI * KCH_U * 32) {
        int ln = idx & 31, kch = (idx >> 5) % KCH_U, nbg = idx / (32 * KCH_U);
        int n = nbg * 8 + (ln >> 2), tk = ln & 3, kb = kch * 16;
        uint4 v; uint32_t* vp = (uint32_t*)&v;
        #pragma unroll
        for (int q = 0; q < 4; ++q) {
            int k = kb + q * 4 + tk;
            float f = (k < HID && n < 900) ? U_iou[k * 900 + n] : 0.0f;
            vp[q] = f2tf(f);
        }
        g_Bi_f[idx] = v;
    }
    if (idx < NBGF * KCH_U * 32) {
        int ln = idx & 31, kch = (idx >> 5) % KCH_U, nbg = idx / (32 * KCH_U);
        int n = nbg * 8 + (ln >> 2), tk = ln & 3, kb = kch * 16;
        uint4 v; uint32_t* vp = (uint32_t*)&v;
        #pragma unroll
        for (int q = 0; q < 4; ++q) {
            int k = kb + q * 4 + tk;
            float f = (k < HID && n < 300) ? U_f[k * 300 + n] : 0.0f;
            vp[q] = f2tf(f);
        }
        g_Bf_f[idx] = v;
    }
}

#define MMA_STEP(ACC, AQ, B0, B1)                                              \
    asm("mma.sync.aligned.m16n8k8.row.col.f32.tf32.tf32.f32 "                  \
        "{%0,%1,%2,%3},{%4,%5,%6,%7},{%8,%9},{%0,%1,%2,%3};"                   \
        : "+f"((ACC)[0]), "+f"((ACC)[1]), "+f"((ACC)[2]), "+f"((ACC)[3])       \
        : "r"((AQ)[0]), "r"((AQ)[1]), "r"((AQ)[2]), "r"((AQ)[3]),              \
          "r"(B0), "r"(B1))

#define LDSM_A(AQ, ASBASE, R0, KB)                                             \
    do {                                                                       \
        const float* _p = (ASBASE) +                                           \
            ((R0) + (lane & 7) + ((lane >> 3) & 1) * 8) * 20 +                 \
            (KB) * 8 + (lane >> 4) * 4;                                        \
        uint32_t _ad = (uint32_t)__cvta_generic_to_shared(_p);                 \
        asm volatile("ldmatrix.sync.aligned.m8n8.x4.shared.b16 "               \
                     "{%0,%1,%2,%3},[%4];"                                     \
                     : "=r"((AQ)[0]), "=r"((AQ)[1]), "=r"((AQ)[2]), "=r"((AQ)[3]) \
                     : "r"(_ad));                                              \
    } while (0)

// ---------------------------------------------------------------------------
// gemm_wx: wx rows [rowOff, rowOff+Mpart) = emb @ [W_iou|W_f] + bias.
// ---------------------------------------------------------------------------
__global__ __launch_bounds__(256, 2) void gemm_wx(
    const float* __restrict__ embedTab, const int* __restrict__ xg,
    int rowOff, int Mpart)
{
    extern __shared__ char smem[];
    float (*As)[128][20] = (float (*)[128][20])smem;
    uint4 (*Bs)[16][32]  = (uint4 (*)[16][32])(smem + 3 * 128 * 80);
    const float** arows  = (const float**)(smem + 3 * 128 * 80 + 3 * 16 * 32 * 16);

    const int tid = threadIdx.x;
    const int rowBase = rowOff + blockIdx.x * 128;
    const int colBase = blockIdx.y * 128;
    const int Mend = rowOff + Mpart;

    if (tid < 128) {
        int m = rowBase + tid;
        int mc = (m < Mend) ? m : (Mend - 1);
        arows[tid] = embedTab + (size_t)xg[mc] * EMB;
    }
    __syncthreads();

    const int lane = tid & 31, warp = tid >> 5;
    const int wm = (warp & 3) * 32, wn = (warp >> 2) * 64;
    const int nbW = wn >> 3;
    const int tg = lane >> 2, tk = lane & 3;
    const int nbgBase = colBase >> 3;

    float acc[2][8][4] = {};

#define FILL_WX(ST, KC)                                                         \
    do {                                                                        \
        int _k0 = (KC) * 16;                                                    \
        _Pragma("unroll")                                                       \
        for (int _i = 0; _i < 2; ++_i) {                                        \
            int _e = tid + _i * 256, _r = _e >> 2, _c = _e & 3;                 \
            uint32_t _d = (uint32_t)__cvta_generic_to_shared(&As[ST][_r][_c*4]);\
            const float* _s = arows[_r] + _k0 + _c * 4;                         \
            int _vb = EMB - (_k0 + _c * 4);                                     \
            int _sz = (_vb >= 4) ? 16 : ((_vb > 0) ? _vb * 4 : 0);              \
            CPA16Z(_d, _s, _sz);                                                \
        }                                                                       \
        _Pragma("unroll")                                                       \
        for (int _i = 0; _i < 2; ++_i) {                                        \
            int _e = tid + _i * 256, _nb = _e >> 5, _ln = _e & 31;              \
            uint32_t _d = (uint32_t)__cvta_generic_to_shared(&Bs[ST][_nb][_ln]);\
            CPA16(_d, g_Bw_f + ((size_t)(nbgBase + _nb) * KCH_E + (KC)) * 32 + _ln); \
        }                                                                       \
        CPCOMMIT();                                                             \
    } while (0)

    FILL_WX(0, 0);
    FILL_WX(1, 1);

    for (int kch = 0; kch < KCH_E; ++kch) {
        const int s = kch % 3;
        if (kch + 1 < KCH_E) { CPWAIT(1); } else { CPWAIT(0); }
        __syncthreads();
        if (kch + 2 < KCH_E) FILL_WX((kch + 2) % 3, kch + 2);

        uint32_t a[2][2][4];
        #pragma unroll
        for (int kb = 0; kb < 2; ++kb)
            #pragma unroll
            for (int mf = 0; mf < 2; ++mf)
                LDSM_A(a[kb][mf], &As[s][0][0], wm + mf * 16, kb);

        #pragma unroll
        for (int nf = 0; nf < 8; ++nf) {
            uint4 bq = Bs[s][nbW + nf][lane];
            #pragma unroll
            for (int mf = 0; mf < 2; ++mf) {
                MMA_STEP(acc[mf][nf], a[0][mf], bq.x, bq.y);
                MMA_STEP(acc[mf][nf], a[1][mf], bq.z, bq.w);
            }
        }
    }
#undef FILL_WX

    #pragma unroll
    for (int mf = 0; mf < 2; ++mf)
        #pragma unroll
        for (int nf = 0; nf < 8; ++nf) {
            int row = rowBase + wm + mf * 16 + tg;
            int col = colBase + wn + nf * 8 + tk * 2;
            if (col < NC) {
                float b0 = g_bias[col], b1 = g_bias[col + 1];
                if (row < Mend)
                    *(float2*)(g_wx + (size_t)row * NC + col) =
                        make_float2(acc[mf][nf][0] + b0, acc[mf][nf][1] + b1);
                if (row + 8 < Mend)
                    *(float2*)(g_wx + (size_t)(row + 8) * NC + col) =
                        make_float2(acc[mf][nf][2] + b0, acc[mf][nf][3] + b1);
            }
        }
}

// ---------------------------------------------------------------------------
// level_gemm: packed 1D grid (no dead blocks).
// Blocks [0, iouX*8): IOU (A=g_Hs, N=900 -> g_Ti), xi = id % iouX, yi = id / iouX.
// Rest: F (A=H children, N=300 -> g_Tf), xi = t % np, yi = t / np.
// ---------------------------------------------------------------------------
__global__ __launch_bounds__(256, 2) void level_gemm(int p0, int np, int iouX)
{
    extern __shared__ char smem[];
    float (*As)[128][20] = (float (*)[128][20])smem;
    uint4 (*Bs)[16][32]  = (uint4 (*)[16][32])(smem + 3 * 128 * 80);

    const int tid = threadIdx.x;
    int id = blockIdx.x;
    const bool isF = (id >= iouX * 8);
    int xi, yi;
    if (isF) { int t = id - iouX * 8; xi = t % np; yi = t / np; }
    else     { xi = id % iouX; yi = id / iouX; }
    const int Mrows = isF ? np * 128 : np * 64;
    const int rowBase = xi * 128;
    const int colBase = yi * 128;
    const int Nout = isF ? 300 : 900;
    const uint4* gB = isF ? g_Bf_f : g_Bi_f;
    float* Cout = isF ? g_Tf : g_Ti;

    const int lane = tid & 31, warp = tid >> 5;
    const int wm = (warp & 3) * 32, wn = (warp >> 2) * 64;
    const int nbW = wn >> 3;
    const int tg = lane >> 2, tk = lane & 3;
    const int nbgBase = colBase >> 3;

    const int ar = tid >> 1;
    const int ac = (tid & 1) << 1;
    int arow = rowBase + ar; if (arow >= Mrows) arow = Mrows - 1;
    const float* asrc = isF
        ? g_H  + (size_t)((2 * p0 + 1) * B_ + arow) * H_LD
        : g_Hs + (size_t)arow * H_LD;

    float acc[2][8][4] = {};

#define FILL_LV(ST, KC)                                                         \
    do {                                                                        \
        int _k0 = (KC) * 16;                                                    \
        _Pragma("unroll")                                                       \
        for (int _i = 0; _i < 2; ++_i) {                                        \
            int _c = ac + _i;                                                   \
            uint32_t _d = (uint32_t)__cvta_generic_to_shared(&As[ST][ar][_c*4]);\
            CPA16(_d, asrc + _k0 + _c * 4);                                     \
        }                                                                       \
        _Pragma("unroll")                                                       \
        for (int _i = 0; _i < 2; ++_i) {                                        \
            int _e = tid + _i * 256, _nb = _e >> 5, _ln = _e & 31;              \
            uint32_t _d = (uint32_t)__cvta_generic_to_shared(&Bs[ST][_nb][_ln]);\
            CPA16(_d, gB + ((size_t)(nbgBase + _nb) * KCH_U + (KC)) * 32 + _ln);\
        }                                                                       \
        CPCOMMIT();                                                             \
    } while (0)

    FILL_LV(0, 0);
    FILL_LV(1, 1);

    for (int kch = 0; kch < KCH_U; ++kch) {
        const int s = kch % 3;
        if (kch + 1 < KCH_U) { CPWAIT(1); } else { CPWAIT(0); }
        __syncthreads();
        if (kch + 2 < KCH_U) FILL_LV((kch + 2) % 3, kch + 2);

        uint32_t a[2][2][4];
        #pragma unroll
        for (int kb = 0; kb < 2; ++kb)
            #pragma unroll
            for (int mf = 0; mf < 2; ++mf)
                LDSM_A(a[kb][mf], &As[s][0][0], wm + mf * 16, kb);

        #pragma unroll
        for (int nf = 0; nf < 8; ++nf) {
            uint4 bq = Bs[s][nbW + nf][lane];
            #pragma unroll
            for (int mf = 0; mf < 2; ++mf) {
                MMA_STEP(acc[mf][nf], a[0][mf], bq.x, bq.y);
                MMA_STEP(acc[mf][nf], a[1][mf], bq.z, bq.w);
            }
        }
    }
#undef FILL_LV

    #pragma unroll
    for (int mf = 0; mf < 2; ++mf)
        #pragma unroll
        for (int nf = 0; nf < 8; ++nf) {
            int row = rowBase + wm + mf * 16 + tg;
            int col = colBase + wn + nf * 8 + tk * 2;
            if (col < Nout) {
                if (row < Mrows)
                    *(float2*)(Cout + (size_t)row * Nout + col) =
                        make_float2(acc[mf][nf][0], acc[mf][nf][1]);
                if (row + 8 < Mrows)
                    *(float2*)(Cout + (size_t)(row + 8) * Nout + col) =
                        make_float2(acc[mf][nf][2], acc[mf][nf][3]);
            }
        }
}

// ---------------------------------------------------------------------------
// Leaves (float4, sibling-paired).
// ---------------------------------------------------------------------------
__global__ void leaf_kernel()
{
    int idx = blockIdx.x * blockDim.x + threadIdx.x;
    if (idx >= 64 * B_ * 75) return;
    int q = idx % 75;
    int r = idx / 75;
    int b = r % B_;
    int j = r / B_;

    float4 hs = make_float4(0.f, 0.f, 0.f, 0.f);
    #pragma unroll
    for (int s = 0; s < 2; ++s) {
        int row = (127 + 2 * j + s) * B_ + b;
        const float4* wx = (const float4*)(g_wx + (size_t)row * NC);
        float4 iv = f4sig (wx[q]);
        float4 ov = f4sig (wx[75 + q]);
        float4 uv = f4tanh(wx[150 + q]);
        float4 c4 = f4mul(iv, uv);
        float4 h4 = f4mul(ov, f4tanh(c4));
        ((float4*)(g_C + (size_t)row * HID))[q] = c4;
        ((float4*)(g_H + (size_t)row * H_LD))[q] = h4;
        hs = f4add(hs, h4);
    }
    ((float4*)(g_Hs + (size_t)r * H_LD))[q] = hs;
}

// ---------------------------------------------------------------------------
// Gate math (float4).
// ---------------------------------------------------------------------------
__device__ __forceinline__ float4 node_gate4(int p0, int pi, int b, int q, float4* cOut)
{
    int p = p0 + pi;
    const float4* wx = (const float4*)(g_wx + (size_t)(p * B_ + b) * NC);
    const float4* ti = (const float4*)(g_Ti + (size_t)(pi * B_ + b) * 900);
    float4 iv = f4sig (f4add(wx[q],       ti[q]));
    float4 ov = f4sig (f4add(wx[75 + q],  ti[75 + q]));
    float4 uv = f4tanh(f4add(wx[150 + q], ti[150 + q]));
    float4 wf = wx[225 + q];
    const float4* tl = (const float4*)(g_Tf + (size_t)((2 * pi    ) * B_ + b) * 300);
    const float4* tr = (const float4*)(g_Tf + (size_t)((2 * pi + 1) * B_ + b) * 300);
    float4 fl = f4sig(f4add(wf, tl[q]));
    float4 fr = f4sig(f4add(wf, tr[q]));
    int lc = 2 * p + 1, rc = 2 * p + 2;
    const float4* cl = (const float4*)(g_C + (size_t)(lc * B_ + b) * HID);
    const float4* cr = (const float4*)(g_C + (size_t)(rc * B_ + b) * HID);
    float4 fc = f4fma(fl, cl[q], f4mul(fr, cr[q]));
    float4 c = f4fma(iv, uv, fc);
    *cOut = c;
    return f4mul(ov, f4tanh(c));
}

__global__ void level_pw_pair(int p0, int np)
{
    int idx = blockIdx.x * blockDim.x + threadIdx.x;
    int tot = (np >> 1) * B_ * 75;
    if (idx >= tot) return;
    int q = idx % 75;
    int r = idx / 75;
    int b = r % B_;
    int i = r / B_;

    float4 cL, cR;
    float4 hL = node_gate4(p0, 2 * i,     b, q, &cL);
    float4 hR = node_gate4(p0, 2 * i + 1, b, q, &cR);

    int pL = p0 + 2 * i, pR = pL + 1;
    ((float4*)(g_C + (size_t)(pL * B_ + b) * HID))[q] = cL;
    ((float4*)(g_C + (size_t)(pR * B_ + b) * HID))[q] = cR;
    ((float4*)(g_H + (size_t)(pL * B_ + b) * H_LD))[q] = hL;
    ((float4*)(g_H + (size_t)(pR * B_ + b) * H_LD))[q] = hR;
    ((float4*)(g_Hs + (size_t)r * H_LD))[q] = f4add(hL, hR);
}

// ---------------------------------------------------------------------------
// root_out: fused root gates + output head (log_softmax over 2 classes).
// ---------------------------------------------------------------------------
__global__ __launch_bounds__(32) void root_out(
    const float* __restrict__ W_out, const float* __restrict__ b_out,
    float* __restrict__ out)
{
    const int b = blockIdx.x;
    const int tid = threadIdx.x;
    float l0 = 0.f, l1 = 0.f;
    for (int q = tid; q < 75; q += 32) {
        float4 c4;
        float4 h4 = node_gate4(0, 0, b, q, &c4);
        int n = q * 4;
        l0 = fmaf(h4.x, W_out[n * 2 + 0], l0); l1 = fmaf(h4.x, W_out[n * 2 + 1], l1);
        l0 = fmaf(h4.y, W_out[n * 2 + 2], l0); l1 = fmaf(h4.y, W_out[n * 2 + 3], l1);
        l0 = fmaf(h4.z, W_out[n * 2 + 4], l0); l1 = fmaf(h4.z, W_out[n * 2 + 5], l1);
        l0 = fmaf(h4.w, W_out[n * 2 + 6], l0); l1 = fmaf(h4.w, W_out[n * 2 + 7], l1);
    }
    #pragma unroll
    for (int o = 16; o > 0; o >>= 1) {
        l0 += __shfl_down_sync(0xffffffffu, l0, o);
        l1 += __shfl_down_sync(0xffffffffu, l1, o);
    }
    if (tid == 0) {
        l0 += b_out[0]; l1 += b_out[1];
        float m   = fmaxf(l0, l1);
        float lse = m + logf(expf(l0 - m) + expf(l1 - m));
        out[b * 2 + 0] = l0 - lse;
        out[b * 2 + 1] = l1 - lse;
    }
}

// ---------------------------------------------------------------------------
extern "C" void kernel_launch(void* const* d_in, const int* in_sizes, int n_in,
                              void* d_out, int out_size)
{
    (void)in_sizes; (void)n_in; (void)out_size;
    const int*   x     = (const int*)  d_in[0];
    const float* embed = (const float*)d_in[3];
    const float* W_iou = (const float*)d_in[4];
    const float* U_iou = (const float*)d_in[5];
    const float* b_iou = (const float*)d_in[6];
    const float* W_f   = (const float*)d_in[7];
    const float* U_f   = (const float*)d_in[8];
    const float* b_f   = (const float*)d_in[9];
    const float* W_out = (const float*)d_in[10];
    const float* b_out = (const float*)d_in[11];

    const int SMEM_WX = 3 * 128 * 80 + 3 * 16 * 32 * 16 + 128 * 8;
    const int SMEM_LV = 3 * 128 * 80 + 3 * 16 * 32 * 16;

    static cudaStream_t s2 = 0;
    static cudaEvent_t evFork = 0, evJoin = 0, evPrep = 0;
    static int inited = 0;
    if (!inited) {
        cudaFuncSetAttribute(gemm_wx,    cudaFuncAttributeMaxDynamicSharedMemorySize, SMEM_WX);
        cudaFuncSetAttribute(level_gemm, cudaFuncAttributeMaxDynamicSharedMemorySize, SMEM_LV);
        int lo, hi;
        cudaDeviceGetStreamPriorityRange(&lo, &hi);
        cudaStreamCreateWithPriority(&s2, cudaStreamNonBlocking, lo);
        cudaEventCreateWithFlags(&evFork, cudaEventDisableTiming);
        cudaEventCreateWithFlags(&evJoin, cudaEventDisableTiming);
        cudaEventCreateWithFlags(&evPrep, cudaEventDisableTiming);
        inited = 1;
    }

    // Critical path: Bw prep -> leaf wx (iou cols only) -> leaf gates -> levels.
    prep_w<<<(NBG0 * KCH_E * 32 + 255) / 256, 256>>>(W_iou, W_f, b_iou, b_f);

    cudaEventRecord(evFork, 0);
    cudaStreamWaitEvent(s2, evFork, 0);
    // s2 (low priority): U prep, then internal-node wx (rows 0..8127, full N).
    prep_u<<<(NBGI * KCH_U * 32 + 255) / 256, 256, 0, s2>>>(U_iou, U_f);
    cudaEventRecord(evPrep, s2);
    gemm_wx<<<dim3(64, 10), 256, SMEM_WX, s2>>>(embed, x, 0, 127 * B_);
    cudaEventRecord(evJoin, s2);

    // Leaf path on stream 0: leaf wx needs only iou cols (900 < 8*128).
    gemm_wx<<<dim3(64, 8), 256, SMEM_WX>>>(embed, x, 127 * B_, 128 * B_);
    leaf_kernel<<<(64 * B_ * 75 + 255) / 256, 256>>>();

    cudaStreamWaitEvent(0, evPrep, 0);   // level GEMMs need Bi/Bf
    {
        int np = 64, p0 = 63;
        int iouX = np / 2;
        level_gemm<<<iouX * 8 + np * 3, 256, SMEM_LV>>>(p0, np, iouX);
        cudaStreamWaitEvent(0, evJoin, 0);   // pw reads internal-node wx
        level_pw_pair<<<((np / 2) * B_ * 75 + 255) / 256, 256>>>(p0, np);
    }

    for (int d = 5; d >= 1; --d) {
        int np = 1 << d;
        int p0 = np - 1;
        int iouX = np / 2;
        level_gemm<<<iouX * 8 + np * 3, 256, SMEM_LV>>>(p0, np, iouX);
        level_pw_pair<<<((np / 2) * B_ * 75 + 255) / 256, 256>>>(p0, np);
    }
    // root: np=1, iouX=1 (one 64-row iou tile block per column tile)
    level_gemm<<<1 * 8 + 1 * 3, 256, SMEM_LV>>>(0, 1, 1);
    root_out<<<64, 32>>>(W_out, b_out, (float*)d_out);
}